// round 1
// baseline (speedup 1.0000x reference)
#include <cuda_runtime.h>
#include <math.h>

#define BB 4
#define CC 256
#define TT 64
#define FF 512
#define HH 8
#define DH 64          // FF/HH

// ---------------- scratch (no allocations allowed) ----------------
__device__ float g_xm[BB*CC*FF];     // time-mean            [b,c,f]
__device__ float g_q [BB*CC*FF];     // q projection         [b,c,f]
__device__ float g_k [BB*CC*FF];     // k projection         [b,c,f]
__device__ float g_w [BB*HH*CC*CC];  // softmax weights      [b,h,c,e]
__device__ float g_s [BB*CC];        // SE gate              [b,c]

// ---------------- K1: xm[b,c,f] = mean_t x[b,c,t,f] ----------------
__global__ void k_mean(const float* __restrict__ x) {
    int bc = blockIdx.x;          // b*CC + c
    int f  = threadIdx.x;         // 512
    const float* p = x + (size_t)bc * TT * FF + f;
    float acc = 0.f;
#pragma unroll
    for (int t = 0; t < TT; ++t) acc += p[t * FF];
    g_xm[(size_t)bc * FF + f] = acc * (1.0f / TT);
}

// ---------------- K2: q = xm@Wq^T + bq ; k = xm@Wk^T ----------------
// A [1024 x 512] = g_xm, B rows = Wq/Wk rows (since we multiply by W^T).
// 64x64 block tile, 256 threads, 4x4 micro-tile per matrix.
__global__ __launch_bounds__(256) void k_proj(const float* __restrict__ Wq,
                                              const float* __restrict__ bq,
                                              const float* __restrict__ Wk) {
    __shared__ float As [16][68];
    __shared__ float Bqs[16][68];
    __shared__ float Bks[16][68];
    int m0 = blockIdx.y * 64;
    int n0 = blockIdx.x * 64;
    int tid = threadIdx.x;
    int ty = tid >> 4, tx = tid & 15;
    float aq[4][4] = {}, ak[4][4] = {};

    for (int k0 = 0; k0 < FF; k0 += 16) {
        int lr = tid >> 2;            // 0..63 row within tile
        int lk = (tid & 3) * 4;       // k offset (float4)
        float4 va = *(const float4*)(g_xm + (size_t)(m0 + lr) * FF + k0 + lk);
        float4 vq = *(const float4*)(Wq   + (size_t)(n0 + lr) * FF + k0 + lk);
        float4 vk = *(const float4*)(Wk   + (size_t)(n0 + lr) * FF + k0 + lk);
        As [lk  ][lr] = va.x; As [lk+1][lr] = va.y; As [lk+2][lr] = va.z; As [lk+3][lr] = va.w;
        Bqs[lk  ][lr] = vq.x; Bqs[lk+1][lr] = vq.y; Bqs[lk+2][lr] = vq.z; Bqs[lk+3][lr] = vq.w;
        Bks[lk  ][lr] = vk.x; Bks[lk+1][lr] = vk.y; Bks[lk+2][lr] = vk.z; Bks[lk+3][lr] = vk.w;
        __syncthreads();
#pragma unroll
        for (int k = 0; k < 16; ++k) {
            float a[4], bqv[4], bkv[4];
#pragma unroll
            for (int i = 0; i < 4; i++) a[i]   = As [k][ty*4 + i];
#pragma unroll
            for (int j = 0; j < 4; j++) bqv[j] = Bqs[k][tx*4 + j];
#pragma unroll
            for (int j = 0; j < 4; j++) bkv[j] = Bks[k][tx*4 + j];
#pragma unroll
            for (int i = 0; i < 4; i++)
#pragma unroll
                for (int j = 0; j < 4; j++) {
                    aq[i][j] += a[i] * bqv[j];
                    ak[i][j] += a[i] * bkv[j];
                }
        }
        __syncthreads();
    }
#pragma unroll
    for (int i = 0; i < 4; i++) {
        int r = m0 + ty*4 + i;
#pragma unroll
        for (int j = 0; j < 4; j++) {
            int c = n0 + tx*4 + j;
            g_q[(size_t)r * FF + c] = aq[i][j] + bq[c];
            g_k[(size_t)r * FF + c] = ak[i][j];
        }
    }
}

// ---------------- K3: qk (scaled) + softmax -> w ----------------
// One block = (b,h, 32 rows). 1024 threads = 32 warps, warp-per-row.
// K tile [256 x 64] in smem, row stride 65 (conflict-free column reads).
__global__ __launch_bounds__(1024) void k_attn() {
    extern __shared__ float Ks[];   // 256*65 floats
    int idx    = blockIdx.x;
    int rowblk = idx & 7;
    int bh     = idx >> 3;          // b*8+h
    int b = bh >> 3, h = bh & 7;
    int tid  = threadIdx.x;
    int lane = tid & 31, wid = tid >> 5;

    {   // cooperative K-tile load (16 float4 per row, 64 rows/pass)
        int f4 = tid & 15;
        int e0 = tid >> 4;
#pragma unroll
        for (int p = 0; p < 4; ++p) {
            int e = e0 + p * 64;
            float4 v = *(const float4*)(g_k + (size_t)(b*CC + e) * FF + h*DH + f4*4);
            Ks[e*65 + f4*4 + 0] = v.x;
            Ks[e*65 + f4*4 + 1] = v.y;
            Ks[e*65 + f4*4 + 2] = v.z;
            Ks[e*65 + f4*4 + 3] = v.w;
        }
    }
    int c = rowblk * 32 + wid;
    float qlo = g_q[(size_t)(b*CC + c) * FF + h*DH + lane];
    float qhi = g_q[(size_t)(b*CC + c) * FF + h*DH + 32 + lane];
    __syncthreads();

    float s[8] = {};
#pragma unroll
    for (int d = 0; d < 32; ++d) {
        float qd = __shfl_sync(0xffffffffu, qlo, d);
#pragma unroll
        for (int i = 0; i < 8; i++) s[i] += qd * Ks[(lane + 32*i)*65 + d];
    }
#pragma unroll
    for (int d = 0; d < 32; ++d) {
        float qd = __shfl_sync(0xffffffffu, qhi, d);
#pragma unroll
        for (int i = 0; i < 8; i++) s[i] += qd * Ks[(lane + 32*i)*65 + 32 + d];
    }
    // scale^2 = (F/h)^(-0.5) = 1/8
    float mx = -1e30f;
#pragma unroll
    for (int i = 0; i < 8; i++) { s[i] *= 0.125f; mx = fmaxf(mx, s[i]); }
#pragma unroll
    for (int off = 16; off; off >>= 1) mx = fmaxf(mx, __shfl_xor_sync(0xffffffffu, mx, off));
    float sum = 0.f;
#pragma unroll
    for (int i = 0; i < 8; i++) { s[i] = __expf(s[i] - mx); sum += s[i]; }
#pragma unroll
    for (int off = 16; off; off >>= 1) sum += __shfl_xor_sync(0xffffffffu, sum, off);
    float inv = 1.0f / sum;
    float* wrow = g_w + ((size_t)bh * CC + c) * CC;
#pragma unroll
    for (int i = 0; i < 8; i++) wrow[lane + 32*i] = s[i] * inv;
}

// ---------------- K4: SE gate, derived WITHOUT materializing y ----------------
// s0[b,c] = (1/F) * sum_h sum_e w[b,h,c,e] * P[e][h],  P[e][h]=sum_{f in h} xm[b,e,f]
__global__ __launch_bounds__(256) void k_se(const float* __restrict__ W1,
                                            const float* __restrict__ W2) {
    __shared__ float P[CC][9];
    __shared__ float s0[CC];
    __shared__ float u[16];
    int b   = blockIdx.x;
    int tid = threadIdx.x;
    {
        const float* p = g_xm + (size_t)(b*CC + tid) * FF;
#pragma unroll
        for (int h = 0; h < HH; ++h) {
            float acc = 0.f;
#pragma unroll
            for (int d = 0; d < DH; ++d) acc += p[h*DH + d];
            P[tid][h] = acc;
        }
    }
    __syncthreads();
    int lane = tid & 31, wid = tid >> 5;
    for (int it = 0; it < 32; ++it) {
        int c = it * 8 + wid;
        float acc = 0.f;
        for (int h = 0; h < HH; ++h) {
            const float* wr = g_w + ((size_t)(b*HH + h) * CC + c) * CC;
#pragma unroll
            for (int j = 0; j < 8; j++) acc += wr[lane + 32*j] * P[lane + 32*j][h];
        }
#pragma unroll
        for (int off = 16; off; off >>= 1) acc += __shfl_xor_sync(0xffffffffu, acc, off);
        if (lane == 0) s0[c] = acc * (1.0f / FF);
    }
    __syncthreads();
    if (tid < 16) {
        float acc = 0.f;
        for (int c = 0; c < CC; ++c) acc += s0[c] * W1[tid*CC + c];
        u[tid] = fmaxf(acc, 0.f);
    }
    __syncthreads();
    {
        float acc = 0.f;
#pragma unroll
        for (int r = 0; r < 16; ++r) acc += u[r] * W2[tid*16 + r];
        g_s[b*CC + tid] = 1.0f / (1.0f + __expf(-acc));
    }
}

// ---------------- K5: out[b,c,t,f] = s[b,c] * sum_e w[b,f/64,c,e]*x[b,e,t,f] --------
// Per (b,h): GEMM M=256(c) x N=4096(t,f') x K=256(e). 128x128 block tile,
// 256 threads, 8x8 micro-tile, K-step 16. Gate scale fused in epilogue.
__global__ __launch_bounds__(256) void k_wv(const float* __restrict__ x,
                                            float* __restrict__ out) {
    __shared__ float As[16][132];   // W^T tile  [k][m]
    __shared__ float Bs[16][128];   // X  tile   [k][n]
    int bh = blockIdx.z;
    int b = bh >> 3, h = bh & 7;
    int m0 = blockIdx.y * 128;
    int n0 = blockIdx.x * 128;      // n = t_local*64 + f'
    int t0 = n0 >> 6;               // covers t0, t0+1
    int tid = threadIdx.x;
    int ty = tid >> 4, tx = tid & 15;

    const float* wptr  = g_w + ((size_t)bh * CC + m0) * CC;
    const float* xbase = x + (size_t)b * CC * TT * FF + h * DH;

    float acc[8][8] = {};

    for (int k0 = 0; k0 < CC; k0 += 16) {
        // load A: 128 m x 16 k (w rows contiguous in e=k)
#pragma unroll
        for (int p = 0; p < 2; ++p) {
            int m = (tid >> 2) + p * 64;
            int k = (tid & 3) * 4;
            float4 v = *(const float4*)(wptr + (size_t)m * CC + k0 + k);
            As[k  ][m] = v.x;
            As[k+1][m] = v.y;
            As[k+2][m] = v.z;
            As[k+3][m] = v.w;
        }
        // load B: 16 e x 128 n ; per row two 64-float chunks at stride FF
#pragma unroll
        for (int p = 0; p < 2; ++p) {
            int e  = (tid >> 5) + p * 8;
            int f4 = tid & 31;
            int n  = f4 * 4;
            int t  = t0 + (n >> 6);
            int fp = n & 63;
            float4 v = *(const float4*)(xbase + ((size_t)(k0 + e) * TT + t) * FF + fp);
            *(float4*)&Bs[e][n] = v;
        }
        __syncthreads();
#pragma unroll
        for (int k = 0; k < 16; ++k) {
            float a[8], bb[8];
#pragma unroll
            for (int i = 0; i < 4; i++) { a[i] = As[k][ty*4 + i]; a[i+4] = As[k][64 + ty*4 + i]; }
#pragma unroll
            for (int j = 0; j < 4; j++) { bb[j] = Bs[k][tx*4 + j]; bb[j+4] = Bs[k][64 + tx*4 + j]; }
#pragma unroll
            for (int i = 0; i < 8; i++)
#pragma unroll
                for (int j = 0; j < 8; j++) acc[i][j] += a[i] * bb[j];
        }
        __syncthreads();
    }

    // epilogue: scale by SE gate, write out[b,c,t,h*64+f']
#pragma unroll
    for (int i = 0; i < 8; i++) {
        int m = (i < 4) ? (ty*4 + i) : (64 + ty*4 + (i - 4));
        int c = m0 + m;
        float sv = g_s[b*CC + c];
        float* obase = out + (size_t)(b*CC + c) * TT * FF + h * DH;
#pragma unroll
        for (int jh = 0; jh < 2; ++jh) {
            int n  = jh * 64 + tx * 4;
            int t  = t0 + (n >> 6);
            int fp = n & 63;
            float4 o;
            o.x = acc[i][jh*4 + 0] * sv;
            o.y = acc[i][jh*4 + 1] * sv;
            o.z = acc[i][jh*4 + 2] * sv;
            o.w = acc[i][jh*4 + 3] * sv;
            *(float4*)(obase + (size_t)t * FF + fp) = o;
        }
    }
}

// ---------------- launch ----------------
extern "C" void kernel_launch(void* const* d_in, const int* in_sizes, int n_in,
                              void* d_out, int out_size) {
    const float* x  = (const float*)d_in[0];
    const float* Wq = (const float*)d_in[1];
    const float* bq = (const float*)d_in[2];
    const float* Wk = (const float*)d_in[3];
    const float* W1 = (const float*)d_in[4];
    const float* W2 = (const float*)d_in[5];
    float* out = (float*)d_out;

    k_mean<<<BB*CC, FF>>>(x);

    dim3 g2(FF/64, (BB*CC)/64);
    k_proj<<<g2, 256>>>(Wq, bq, Wk);

    const int smem3 = CC * 65 * sizeof(float);   // 66560 B
    cudaFuncSetAttribute(k_attn, cudaFuncAttributeMaxDynamicSharedMemorySize, smem3);
    k_attn<<<BB*HH*(CC/32), 1024, smem3>>>();

    k_se<<<BB, 256>>>(W1, W2);

    dim3 g5((TT*DH)/128, CC/128, BB*HH);
    k_wv<<<g5, 256>>>(x, out);
}

// round 3
// speedup vs baseline: 2.3182x; 2.3182x over previous
#include <cuda_runtime.h>
#include <math.h>
#include <stdint.h>

#define BB 4
#define CC 256
#define TT 64
#define FF 512
#define HH 8
#define DH 64          // FF/HH

// ---------------- scratch (no allocations allowed) ----------------
__device__ float g_xm[BB*CC*FF];     // time-mean            [b,c,f]
__device__ float g_q [BB*CC*FF];     // q projection         [b,c,f]
__device__ float g_k [BB*CC*FF];     // k projection         [b,c,f]
__device__ float g_w [BB*HH*CC*CC];  // softmax weights      [b,h,c,e]
__device__ float g_P [BB*CC*HH];     // head-sums of xm      [b,e,h]
__device__ float g_s0[BB*CC];        // pooled y (pre-MLP)   [b,c]
__device__ float g_s [BB*CC];        // SE gate              [b,c]

// ---------------- helpers ----------------
__device__ __forceinline__ uint32_t f2tf(float f) {
    uint32_t u;
    asm("cvt.rna.tf32.f32 %0, %1;" : "=r"(u) : "f"(f));
    return u;
}
__device__ __forceinline__ void mma_tf32(float* c, const uint32_t* a, const uint32_t* b) {
    asm volatile(
        "mma.sync.aligned.m16n8k8.row.col.f32.tf32.tf32.f32 "
        "{%0,%1,%2,%3}, {%4,%5,%6,%7}, {%8,%9}, {%0,%1,%2,%3};\n"
        : "+f"(c[0]), "+f"(c[1]), "+f"(c[2]), "+f"(c[3])
        : "r"(a[0]), "r"(a[1]), "r"(a[2]), "r"(a[3]), "r"(b[0]), "r"(b[1]));
}
#define CP_ASYNC16(dst_u32, src_ptr) \
    asm volatile("cp.async.ca.shared.global [%0], [%1], 16;\n" :: "r"(dst_u32), "l"(src_ptr))
#define CP_COMMIT()  asm volatile("cp.async.commit_group;\n" ::: "memory")
#define CP_WAIT0()   asm volatile("cp.async.wait_group 0;\n" ::: "memory")

// ---------------- K1: xm + head-sums P + zero s0 ----------------
__global__ void k_mean(const float* __restrict__ x) {
    int bc = blockIdx.x;          // b*CC + c
    int f  = threadIdx.x;         // 512
    int lane = f & 31, wid = f >> 5;   // 16 warps; head h spans warps 2h,2h+1
    const float* p = x + (size_t)bc * TT * FF + f;
    float acc = 0.f;
#pragma unroll
    for (int t = 0; t < TT; ++t) acc += p[t * FF];
    float m = acc * (1.0f / TT);
    g_xm[(size_t)bc * FF + f] = m;
    // reduce within warps, then combine pairs of warps -> per-head sums
    __shared__ float red[16];
    float v = m;
#pragma unroll
    for (int off = 16; off; off >>= 1) v += __shfl_xor_sync(0xffffffffu, v, off);
    if (lane == 0) red[wid] = v;
    __syncthreads();
    if (f < HH) g_P[(size_t)bc * HH + f] = red[2*f] + red[2*f + 1];
    if (f == HH) g_s0[bc] = 0.f;
}

// ---------------- K2: q = xm@Wq^T + bq ; k = xm@Wk^T ----------------
__global__ __launch_bounds__(256) void k_proj(const float* __restrict__ Wq,
                                              const float* __restrict__ bq,
                                              const float* __restrict__ Wk) {
    __shared__ float As [16][68];
    __shared__ float Bqs[16][68];
    __shared__ float Bks[16][68];
    int m0 = blockIdx.y * 64;
    int n0 = blockIdx.x * 64;
    int tid = threadIdx.x;
    int ty = tid >> 4, tx = tid & 15;
    float aq[4][4] = {}, ak[4][4] = {};

    for (int k0 = 0; k0 < FF; k0 += 16) {
        int lr = tid >> 2;
        int lk = (tid & 3) * 4;
        float4 va = *(const float4*)(g_xm + (size_t)(m0 + lr) * FF + k0 + lk);
        float4 vq = *(const float4*)(Wq   + (size_t)(n0 + lr) * FF + k0 + lk);
        float4 vk = *(const float4*)(Wk   + (size_t)(n0 + lr) * FF + k0 + lk);
        As [lk  ][lr] = va.x; As [lk+1][lr] = va.y; As [lk+2][lr] = va.z; As [lk+3][lr] = va.w;
        Bqs[lk  ][lr] = vq.x; Bqs[lk+1][lr] = vq.y; Bqs[lk+2][lr] = vq.z; Bqs[lk+3][lr] = vq.w;
        Bks[lk  ][lr] = vk.x; Bks[lk+1][lr] = vk.y; Bks[lk+2][lr] = vk.z; Bks[lk+3][lr] = vk.w;
        __syncthreads();
#pragma unroll
        for (int k = 0; k < 16; ++k) {
            float a[4], bqv[4], bkv[4];
#pragma unroll
            for (int i = 0; i < 4; i++) a[i]   = As [k][ty*4 + i];
#pragma unroll
            for (int j = 0; j < 4; j++) bqv[j] = Bqs[k][tx*4 + j];
#pragma unroll
            for (int j = 0; j < 4; j++) bkv[j] = Bks[k][tx*4 + j];
#pragma unroll
            for (int i = 0; i < 4; i++)
#pragma unroll
                for (int j = 0; j < 4; j++) {
                    aq[i][j] += a[i] * bqv[j];
                    ak[i][j] += a[i] * bkv[j];
                }
        }
        __syncthreads();
    }
#pragma unroll
    for (int i = 0; i < 4; i++) {
        int r = m0 + ty*4 + i;
#pragma unroll
        for (int j = 0; j < 4; j++) {
            int c = n0 + tx*4 + j;
            g_q[(size_t)r * FF + c] = aq[i][j] + bq[c];
            g_k[(size_t)r * FF + c] = ak[i][j];
        }
    }
}

// ---------------- K3: qk + softmax -> w, plus s0 partial (fused SE pool) ----
__global__ __launch_bounds__(1024) void k_attn() {
    extern __shared__ float Ks[];   // 256*65 floats
    int idx    = blockIdx.x;
    int rowblk = idx & 7;
    int bh     = idx >> 3;
    int b = bh >> 3, h = bh & 7;
    int tid  = threadIdx.x;
    int lane = tid & 31, wid = tid >> 5;

    {
        int f4 = tid & 15;
        int e0 = tid >> 4;
#pragma unroll
        for (int p = 0; p < 4; ++p) {
            int e = e0 + p * 64;
            float4 v = *(const float4*)(g_k + (size_t)(b*CC + e) * FF + h*DH + f4*4);
            Ks[e*65 + f4*4 + 0] = v.x;
            Ks[e*65 + f4*4 + 1] = v.y;
            Ks[e*65 + f4*4 + 2] = v.z;
            Ks[e*65 + f4*4 + 3] = v.w;
        }
    }
    int c = rowblk * 32 + wid;
    float qlo = g_q[(size_t)(b*CC + c) * FF + h*DH + lane];
    float qhi = g_q[(size_t)(b*CC + c) * FF + h*DH + 32 + lane];
    __syncthreads();

    float s[8] = {};
#pragma unroll
    for (int d = 0; d < 32; ++d) {
        float qd = __shfl_sync(0xffffffffu, qlo, d);
#pragma unroll
        for (int i = 0; i < 8; i++) s[i] += qd * Ks[(lane + 32*i)*65 + d];
    }
#pragma unroll
    for (int d = 0; d < 32; ++d) {
        float qd = __shfl_sync(0xffffffffu, qhi, d);
#pragma unroll
        for (int i = 0; i < 8; i++) s[i] += qd * Ks[(lane + 32*i)*65 + 32 + d];
    }
    float mx = -1e30f;
#pragma unroll
    for (int i = 0; i < 8; i++) { s[i] *= 0.125f; mx = fmaxf(mx, s[i]); }
#pragma unroll
    for (int off = 16; off; off >>= 1) mx = fmaxf(mx, __shfl_xor_sync(0xffffffffu, mx, off));
    float sum = 0.f;
#pragma unroll
    for (int i = 0; i < 8; i++) { s[i] = __expf(s[i] - mx); sum += s[i]; }
#pragma unroll
    for (int off = 16; off; off >>= 1) sum += __shfl_xor_sync(0xffffffffu, sum, off);
    float inv = 1.0f / sum;
    float* wrow = g_w + ((size_t)bh * CC + c) * CC;
    float part = 0.f;
#pragma unroll
    for (int i = 0; i < 8; i++) {
        int e = lane + 32*i;
        wrow[e] = s[i] * inv;
        part += s[i] * g_P[(size_t)(b*CC + e) * HH + h];
    }
#pragma unroll
    for (int off = 16; off; off >>= 1) part += __shfl_xor_sync(0xffffffffu, part, off);
    if (lane == 0) atomicAdd(&g_s0[b*CC + c], part * inv * (1.0f / FF));
}

// ---------------- K4: tiny SE MLP only ----------------
__global__ __launch_bounds__(256) void k_se2(const float* __restrict__ W1,
                                             const float* __restrict__ W2) {
    __shared__ float s0s[CC];
    __shared__ float u[16];
    int b = blockIdx.x;
    int tid = threadIdx.x;
    int lane = tid & 31, wid = tid >> 5;
    s0s[tid] = g_s0[b*CC + tid];
    __syncthreads();
#pragma unroll
    for (int rr = 0; rr < 2; ++rr) {
        int r = wid + rr * 8;
        float acc = 0.f;
#pragma unroll
        for (int j = 0; j < 8; j++) acc += s0s[lane + 32*j] * W1[r*CC + lane + 32*j];
#pragma unroll
        for (int off = 16; off; off >>= 1) acc += __shfl_xor_sync(0xffffffffu, acc, off);
        if (lane == 0) u[r] = fmaxf(acc, 0.f);
    }
    __syncthreads();
    float acc = 0.f;
#pragma unroll
    for (int r = 0; r < 16; ++r) acc += u[r] * W2[tid*16 + r];
    g_s[b*CC + tid] = 1.0f / (1.0f + __expf(-acc));
}

// ---------------- K5: tf32 tensor-core GEMM with fused gate ----------------
// Per (b,h): D[256(c) x 4096(t,f')] = W[256x256(e)] @ X[256(e) x 4096], scaled by s[b,c].
// 128x128x16 block tiles, 8 warps (4x2), warp tile 32x64, mma m16n8k8 tf32,
// cp.async double buffering.
__global__ __launch_bounds__(256) void k_wv(const float* __restrict__ x,
                                            float* __restrict__ out) {
    __shared__ float As[2][128][20];   // [buf][m][k]  pad->20 (80B rows, 16B aligned)
    __shared__ float Bs[2][16][136];   // [buf][k][n]  pad->136 (544B rows)

    int bh = blockIdx.z;
    int b = bh >> 3, h = bh & 7;
    int m0 = blockIdx.y * 128;
    int n0 = blockIdx.x * 128;
    int t0 = n0 >> 6;
    int tid = threadIdx.x;
    int lane = tid & 31, wid = tid >> 5;
    int warpM = wid >> 1, warpN = wid & 1;
    int r = lane >> 2, cq = lane & 3;

    const float* wptr  = g_w + ((size_t)bh * CC + m0) * CC;
    const float* xbase = x + (size_t)b * CC * TT * FF + h * DH;

    float acc[2][8][4];
#pragma unroll
    for (int i = 0; i < 2; i++)
#pragma unroll
        for (int j = 0; j < 8; j++)
#pragma unroll
            for (int q = 0; q < 4; q++) acc[i][j][q] = 0.f;

    uint32_t as_base = (uint32_t)__cvta_generic_to_shared(&As[0][0][0]);
    uint32_t bs_base = (uint32_t)__cvta_generic_to_shared(&Bs[0][0][0]);
    const uint32_t AS_STAGE = 128 * 20 * 4;
    const uint32_t BS_STAGE = 16 * 136 * 4;

#define LOAD_STAGE(K0, BUF)                                                     \
    do {                                                                        \
        _Pragma("unroll")                                                       \
        for (int p = 0; p < 2; ++p) {                                           \
            int lin = p * 256 + tid;                                            \
            int m = lin >> 2, ck = (lin & 3) * 4;                               \
            const float* g = wptr + (size_t)m * CC + (K0) + ck;                 \
            uint32_t d = as_base + (BUF) * AS_STAGE + (m * 20 + ck) * 4;        \
            CP_ASYNC16(d, g);                                                   \
        }                                                                       \
        _Pragma("unroll")                                                       \
        for (int p = 0; p < 2; ++p) {                                           \
            int lin = p * 256 + tid;                                            \
            int e = lin >> 5; int n = (lin & 31) * 4;                           \
            int t = t0 + (n >> 6); int fp = n & 63;                             \
            const float* g = xbase + ((size_t)((K0) + e) * TT + t) * FF + fp;   \
            uint32_t d = bs_base + (BUF) * BS_STAGE + (e * 136 + n) * 4;        \
            CP_ASYNC16(d, g);                                                   \
        }                                                                       \
        CP_COMMIT();                                                            \
    } while (0)

    LOAD_STAGE(0, 0);
    int buf = 0;

    for (int it = 0; it < 16; ++it) {
        CP_WAIT0();
        __syncthreads();
        if (it < 15) LOAD_STAGE((it + 1) * 16, buf ^ 1);

#pragma unroll
        for (int kk = 0; kk < 2; ++kk) {
            int kb = kk * 8;
            uint32_t a[2][4];
#pragma unroll
            for (int mt = 0; mt < 2; ++mt) {
                int mb = warpM * 32 + mt * 16;
                a[mt][0] = f2tf(As[buf][mb + r    ][kb + cq    ]);
                a[mt][1] = f2tf(As[buf][mb + r + 8][kb + cq    ]);
                a[mt][2] = f2tf(As[buf][mb + r    ][kb + cq + 4]);
                a[mt][3] = f2tf(As[buf][mb + r + 8][kb + cq + 4]);
            }
            uint32_t bf[8][2];
#pragma unroll
            for (int nt = 0; nt < 8; ++nt) {
                int nb = warpN * 64 + nt * 8 + r;
                bf[nt][0] = f2tf(Bs[buf][kb + cq    ][nb]);
                bf[nt][1] = f2tf(Bs[buf][kb + cq + 4][nb]);
            }
#pragma unroll
            for (int mt = 0; mt < 2; ++mt)
#pragma unroll
                for (int nt = 0; nt < 8; ++nt)
                    mma_tf32(acc[mt][nt], a[mt], bf[nt]);
        }
        buf ^= 1;
    }

    // epilogue: gate scale + scattered (t,f') writes
#pragma unroll
    for (int mt = 0; mt < 2; ++mt) {
        int c0 = m0 + warpM * 32 + mt * 16 + r;
        int c1 = c0 + 8;
        float s0v = g_s[b*CC + c0];
        float s1v = g_s[b*CC + c1];
        float* ob0 = out + (size_t)(b*CC + c0) * TT * FF + h * DH;
        float* ob1 = out + (size_t)(b*CC + c1) * TT * FF + h * DH;
#pragma unroll
        for (int nt = 0; nt < 8; ++nt) {
            int nloc = warpN * 64 + nt * 8 + cq * 2;
            int ng = n0 + nloc;
            int t = ng >> 6, fp = ng & 63;
            float2 v0 = { acc[mt][nt][0] * s0v, acc[mt][nt][1] * s0v };
            float2 v1 = { acc[mt][nt][2] * s1v, acc[mt][nt][3] * s1v };
            *(float2*)(ob0 + (size_t)t * FF + fp) = v0;
            *(float2*)(ob1 + (size_t)t * FF + fp) = v1;
        }
    }
#undef LOAD_STAGE
}

// ---------------- launch ----------------
extern "C" void kernel_launch(void* const* d_in, const int* in_sizes, int n_in,
                              void* d_out, int out_size) {
    const float* x  = (const float*)d_in[0];
    const float* Wq = (const float*)d_in[1];
    const float* bq = (const float*)d_in[2];
    const float* Wk = (const float*)d_in[3];
    const float* W1 = (const float*)d_in[4];
    const float* W2 = (const float*)d_in[5];
    float* out = (float*)d_out;

    k_mean<<<BB*CC, FF>>>(x);

    dim3 g2(FF/64, (BB*CC)/64);
    k_proj<<<g2, 256>>>(Wq, bq, Wk);

    const int smem3 = CC * 65 * sizeof(float);
    cudaFuncSetAttribute(k_attn, cudaFuncAttributeMaxDynamicSharedMemorySize, smem3);
    k_attn<<<BB*HH*(CC/32), 1024, smem3>>>();

    k_se2<<<BB, 256>>>(W1, W2);

    dim3 g5((TT*DH)/128, CC/128, BB*HH);
    k_wv<<<g5, 256>>>(x, out);
}

// round 5
// speedup vs baseline: 2.3360x; 1.0077x over previous
#include <cuda_runtime.h>
#include <math.h>
#include <stdint.h>

#define BB 4
#define CC 256
#define TT 64
#define FF 512
#define HH 8
#define DH 64          // FF/HH

// ---------------- scratch (no allocations allowed) ----------------
__device__ float g_xm[BB*CC*FF];     // time-mean            [b,c,f]
__device__ float g_q [BB*CC*FF];     // q projection         [b,c,f]
__device__ float g_k [BB*CC*FF];     // k projection         [b,c,f]
__device__ float g_w [BB*HH*CC*CC];  // softmax weights      [b,h,c,e]
__device__ float g_P [BB*CC*HH];     // head-sums of xm      [b,e,h]
__device__ float g_s0[BB*CC];        // pooled y (pre-MLP)   [b,c]
__device__ float g_s [BB*CC];        // SE gate              [b,c]

// ---------------- helpers ----------------
__device__ __forceinline__ uint32_t f2tf(float f) {
    uint32_t u;
    asm("cvt.rna.tf32.f32 %0, %1;" : "=r"(u) : "f"(f));
    return u;
}
__device__ __forceinline__ void mma_tf32(float* c, const uint32_t* a, const uint32_t* b) {
    asm volatile(
        "mma.sync.aligned.m16n8k8.row.col.f32.tf32.tf32.f32 "
        "{%0,%1,%2,%3}, {%4,%5,%6,%7}, {%8,%9}, {%0,%1,%2,%3};\n"
        : "+f"(c[0]), "+f"(c[1]), "+f"(c[2]), "+f"(c[3])
        : "r"(a[0]), "r"(a[1]), "r"(a[2]), "r"(a[3]), "r"(b[0]), "r"(b[1]));
}
#define CP_ASYNC16(dst_u32, src_ptr) \
    asm volatile("cp.async.ca.shared.global [%0], [%1], 16;\n" :: "r"(dst_u32), "l"(src_ptr))
#define CP_COMMIT()  asm volatile("cp.async.commit_group;\n" ::: "memory")
#define CP_WAIT0()   asm volatile("cp.async.wait_group 0;\n" ::: "memory")
#define CP_WAIT1()   asm volatile("cp.async.wait_group 1;\n" ::: "memory")

// ---------------- K1: xm + head-sums P + zero s0 ----------------
__global__ void k_mean(const float* __restrict__ x) {
    int bc = blockIdx.x;          // b*CC + c
    int f  = threadIdx.x;         // 512
    int lane = f & 31, wid = f >> 5;
    const float* p = x + (size_t)bc * TT * FF + f;
    float acc = 0.f;
#pragma unroll
    for (int t = 0; t < TT; ++t) acc += p[t * FF];
    float m = acc * (1.0f / TT);
    g_xm[(size_t)bc * FF + f] = m;
    __shared__ float red[16];
    float v = m;
#pragma unroll
    for (int off = 16; off; off >>= 1) v += __shfl_xor_sync(0xffffffffu, v, off);
    if (lane == 0) red[wid] = v;
    __syncthreads();
    if (f < HH) g_P[(size_t)bc * HH + f] = red[2*f] + red[2*f + 1];
    if (f == HH) g_s0[bc] = 0.f;
}

// ---------------- K2: q = xm@Wq^T + bq ; k = xm@Wk^T ----------------
__global__ __launch_bounds__(256) void k_proj(const float* __restrict__ Wq,
                                              const float* __restrict__ bq,
                                              const float* __restrict__ Wk) {
    __shared__ float As [16][68];
    __shared__ float Bqs[16][68];
    __shared__ float Bks[16][68];
    int m0 = blockIdx.y * 64;
    int n0 = blockIdx.x * 64;
    int tid = threadIdx.x;
    int ty = tid >> 4, tx = tid & 15;
    float aq[4][4] = {}, ak[4][4] = {};

    for (int k0 = 0; k0 < FF; k0 += 16) {
        int lr = tid >> 2;
        int lk = (tid & 3) * 4;
        float4 va = *(const float4*)(g_xm + (size_t)(m0 + lr) * FF + k0 + lk);
        float4 vq = *(const float4*)(Wq   + (size_t)(n0 + lr) * FF + k0 + lk);
        float4 vk = *(const float4*)(Wk   + (size_t)(n0 + lr) * FF + k0 + lk);
        As [lk  ][lr] = va.x; As [lk+1][lr] = va.y; As [lk+2][lr] = va.z; As [lk+3][lr] = va.w;
        Bqs[lk  ][lr] = vq.x; Bqs[lk+1][lr] = vq.y; Bqs[lk+2][lr] = vq.z; Bqs[lk+3][lr] = vq.w;
        Bks[lk  ][lr] = vk.x; Bks[lk+1][lr] = vk.y; Bks[lk+2][lr] = vk.z; Bks[lk+3][lr] = vk.w;
        __syncthreads();
#pragma unroll
        for (int k = 0; k < 16; ++k) {
            float a[4], bqv[4], bkv[4];
#pragma unroll
            for (int i = 0; i < 4; i++) a[i]   = As [k][ty*4 + i];
#pragma unroll
            for (int j = 0; j < 4; j++) bqv[j] = Bqs[k][tx*4 + j];
#pragma unroll
            for (int j = 0; j < 4; j++) bkv[j] = Bks[k][tx*4 + j];
#pragma unroll
            for (int i = 0; i < 4; i++)
#pragma unroll
                for (int j = 0; j < 4; j++) {
                    aq[i][j] += a[i] * bqv[j];
                    ak[i][j] += a[i] * bkv[j];
                }
        }
        __syncthreads();
    }
#pragma unroll
    for (int i = 0; i < 4; i++) {
        int r = m0 + ty*4 + i;
#pragma unroll
        for (int j = 0; j < 4; j++) {
            int c = n0 + tx*4 + j;
            g_q[(size_t)r * FF + c] = aq[i][j] + bq[c];
            g_k[(size_t)r * FF + c] = ak[i][j];
        }
    }
}

// ---------------- K3: qk + softmax -> w, plus s0 partial (fused SE pool) ----
__global__ __launch_bounds__(1024) void k_attn() {
    extern __shared__ float Ks[];   // 256*65 floats
    int idx    = blockIdx.x;
    int rowblk = idx & 7;
    int bh     = idx >> 3;
    int b = bh >> 3, h = bh & 7;
    int tid  = threadIdx.x;
    int lane = tid & 31, wid = tid >> 5;

    {
        int f4 = tid & 15;
        int e0 = tid >> 4;
#pragma unroll
        for (int p = 0; p < 4; ++p) {
            int e = e0 + p * 64;
            float4 v = *(const float4*)(g_k + (size_t)(b*CC + e) * FF + h*DH + f4*4);
            Ks[e*65 + f4*4 + 0] = v.x;
            Ks[e*65 + f4*4 + 1] = v.y;
            Ks[e*65 + f4*4 + 2] = v.z;
            Ks[e*65 + f4*4 + 3] = v.w;
        }
    }
    int c = rowblk * 32 + wid;
    float qlo = g_q[(size_t)(b*CC + c) * FF + h*DH + lane];
    float qhi = g_q[(size_t)(b*CC + c) * FF + h*DH + 32 + lane];
    __syncthreads();

    float s[8] = {};
#pragma unroll
    for (int d = 0; d < 32; ++d) {
        float qd = __shfl_sync(0xffffffffu, qlo, d);
#pragma unroll
        for (int i = 0; i < 8; i++) s[i] += qd * Ks[(lane + 32*i)*65 + d];
    }
#pragma unroll
    for (int d = 0; d < 32; ++d) {
        float qd = __shfl_sync(0xffffffffu, qhi, d);
#pragma unroll
        for (int i = 0; i < 8; i++) s[i] += qd * Ks[(lane + 32*i)*65 + 32 + d];
    }
    float mx = -1e30f;
#pragma unroll
    for (int i = 0; i < 8; i++) { s[i] *= 0.125f; mx = fmaxf(mx, s[i]); }
#pragma unroll
    for (int off = 16; off; off >>= 1) mx = fmaxf(mx, __shfl_xor_sync(0xffffffffu, mx, off));
    float sum = 0.f;
#pragma unroll
    for (int i = 0; i < 8; i++) { s[i] = __expf(s[i] - mx); sum += s[i]; }
#pragma unroll
    for (int off = 16; off; off >>= 1) sum += __shfl_xor_sync(0xffffffffu, sum, off);
    float inv = 1.0f / sum;
    float* wrow = g_w + ((size_t)bh * CC + c) * CC;
    float part = 0.f;
#pragma unroll
    for (int i = 0; i < 8; i++) {
        int e = lane + 32*i;
        wrow[e] = s[i] * inv;
        part += s[i] * g_P[(size_t)(b*CC + e) * HH + h];
    }
#pragma unroll
    for (int off = 16; off; off >>= 1) part += __shfl_xor_sync(0xffffffffu, part, off);
    if (lane == 0) atomicAdd(&g_s0[b*CC + c], part * inv * (1.0f / FF));
}

// ---------------- K4: tiny SE MLP only ----------------
__global__ __launch_bounds__(256) void k_se2(const float* __restrict__ W1,
                                             const float* __restrict__ W2) {
    __shared__ float s0s[CC];
    __shared__ float u[16];
    int b = blockIdx.x;
    int tid = threadIdx.x;
    int lane = tid & 31, wid = tid >> 5;
    s0s[tid] = g_s0[b*CC + tid];
    __syncthreads();
#pragma unroll
    for (int rr = 0; rr < 2; ++rr) {
        int r = wid + rr * 8;
        float acc = 0.f;
#pragma unroll
        for (int j = 0; j < 8; j++) acc += s0s[lane + 32*j] * W1[r*CC + lane + 32*j];
#pragma unroll
        for (int off = 16; off; off >>= 1) acc += __shfl_xor_sync(0xffffffffu, acc, off);
        if (lane == 0) u[r] = fmaxf(acc, 0.f);
    }
    __syncthreads();
    float acc = 0.f;
#pragma unroll
    for (int r = 0; r < 16; ++r) acc += u[r] * W2[tid*16 + r];
    g_s[b*CC + tid] = 1.0f / (1.0f + __expf(-acc));
}

// ---------------- K5: tf32 tensor-core GEMM with fused gate ----------------
// Per (b,h): D[256(c) x 4096(t,f')] = W[256x256(e)] @ X[256(e) x 4096] * s[b,c].
// BM=256 (full C -> X read exactly once), BN=128, BK=16, 3-stage cp.async.
// 8 warps (4x2): warp tile 64x64, mma m16n8k8 tf32.
#define AS_STRIDE 20
#define BS_STRIDE 136
#define AS_STAGE_F (256 * AS_STRIDE)          // floats per A stage
#define BS_STAGE_F (16 * BS_STRIDE)
#define NSTAGE 3
#define SMEM_WV ((NSTAGE * (AS_STAGE_F + BS_STAGE_F)) * 4)

__global__ __launch_bounds__(256, 1) void k_wv(const float* __restrict__ x,
                                               float* __restrict__ out) {
    extern __shared__ float sm[];
    float* Asm = sm;                           // [NSTAGE][256][20]
    float* Bsm = sm + NSTAGE * AS_STAGE_F;     // [NSTAGE][16][136]

    int bh = blockIdx.z;
    int b = bh >> 3, h = bh & 7;
    int n0 = blockIdx.x * 128;
    int t0 = n0 >> 6;
    int tid = threadIdx.x;
    int lane = tid & 31, wid = tid >> 5;
    int warpM = wid >> 1, warpN = wid & 1;     // warp tile 64(m) x 64(n)
    int r = lane >> 2, cq = lane & 3;

    const float* wptr  = g_w + (size_t)bh * CC * CC;
    const float* xbase = x + (size_t)b * CC * TT * FF + h * DH;

    float acc[4][8][4];
#pragma unroll
    for (int i = 0; i < 4; i++)
#pragma unroll
        for (int j = 0; j < 8; j++)
#pragma unroll
            for (int q = 0; q < 4; q++) acc[i][j][q] = 0.f;

    uint32_t as_base = (uint32_t)__cvta_generic_to_shared(Asm);
    uint32_t bs_base = (uint32_t)__cvta_generic_to_shared(Bsm);

#define LOAD_STAGE(K0, BUF)                                                     \
    do {                                                                        \
        _Pragma("unroll")                                                       \
        for (int p = 0; p < 4; ++p) {                                           \
            int lin = p * 256 + tid;                                            \
            int m = lin >> 2, ck = (lin & 3) * 4;                               \
            const float* g = wptr + (size_t)m * CC + (K0) + ck;                 \
            uint32_t d = as_base + ((BUF) * AS_STAGE_F + m * AS_STRIDE + ck) * 4;\
            CP_ASYNC16(d, g);                                                   \
        }                                                                       \
        _Pragma("unroll")                                                       \
        for (int p = 0; p < 2; ++p) {                                           \
            int lin = p * 256 + tid;                                            \
            int e = lin >> 5; int n = (lin & 31) * 4;                           \
            int t = t0 + (n >> 6); int fp = n & 63;                             \
            const float* g = xbase + ((size_t)((K0) + e) * TT + t) * FF + fp;   \
            uint32_t d = bs_base + ((BUF) * BS_STAGE_F + e * BS_STRIDE + n) * 4;\
            CP_ASYNC16(d, g);                                                   \
        }                                                                       \
        CP_COMMIT();                                                            \
    } while (0)

    LOAD_STAGE(0, 0);
    LOAD_STAGE(16, 1);

    for (int it = 0; it < 16; ++it) {
        CP_WAIT1();                 // stage `it` resident (<=1 group in flight)
        __syncthreads();            // also protects buffer (it+2)%3 = (it-1)%3 reuse
        if (it < 14) LOAD_STAGE((it + 2) * 16, (it + 2) % NSTAGE);
        int buf = it % NSTAGE;
        const float* Ab = Asm + buf * AS_STAGE_F;
        const float* Bb = Bsm + buf * BS_STAGE_F;

#pragma unroll
        for (int kk = 0; kk < 2; ++kk) {
            int kb = kk * 8;
            uint32_t a[4][4];
#pragma unroll
            for (int mt = 0; mt < 4; ++mt) {
                int mb = warpM * 64 + mt * 16;
                a[mt][0] = f2tf(Ab[(mb + r    ) * AS_STRIDE + kb + cq    ]);
                a[mt][1] = f2tf(Ab[(mb + r + 8) * AS_STRIDE + kb + cq    ]);
                a[mt][2] = f2tf(Ab[(mb + r    ) * AS_STRIDE + kb + cq + 4]);
                a[mt][3] = f2tf(Ab[(mb + r + 8) * AS_STRIDE + kb + cq + 4]);
            }
            uint32_t bf[8][2];
#pragma unroll
            for (int nt = 0; nt < 8; ++nt) {
                int nb = warpN * 64 + nt * 8 + r;
                bf[nt][0] = f2tf(Bb[(kb + cq    ) * BS_STRIDE + nb]);
                bf[nt][1] = f2tf(Bb[(kb + cq + 4) * BS_STRIDE + nb]);
            }
#pragma unroll
            for (int mt = 0; mt < 4; ++mt)
#pragma unroll
                for (int nt = 0; nt < 8; ++nt)
                    mma_tf32(acc[mt][nt], a[mt], bf[nt]);
        }
    }
    CP_WAIT0();

    // epilogue: gate scale + (t,f') writes
#pragma unroll
    for (int mt = 0; mt < 4; ++mt) {
        int c0 = warpM * 64 + mt * 16 + r;
        int c1 = c0 + 8;
        float s0v = g_s[b*CC + c0];
        float s1v = g_s[b*CC + c1];
        float* ob0 = out + (size_t)(b*CC + c0) * TT * FF + h * DH;
        float* ob1 = out + (size_t)(b*CC + c1) * TT * FF + h * DH;
#pragma unroll
        for (int nt = 0; nt < 8; ++nt) {
            int nloc = warpN * 64 + nt * 8 + cq * 2;
            int ng = n0 + nloc;
            int t = ng >> 6, fp = ng & 63;
            float2 v0 = { acc[mt][nt][0] * s0v, acc[mt][nt][1] * s0v };
            float2 v1 = { acc[mt][nt][2] * s1v, acc[mt][nt][3] * s1v };
            *(float2*)(ob0 + (size_t)t * FF + fp) = v0;
            *(float2*)(ob1 + (size_t)t * FF + fp) = v1;
        }
    }
#undef LOAD_STAGE
}

// ---------------- launch ----------------
extern "C" void kernel_launch(void* const* d_in, const int* in_sizes, int n_in,
                              void* d_out, int out_size) {
    const float* x  = (const float*)d_in[0];
    const float* Wq = (const float*)d_in[1];
    const float* bq = (const float*)d_in[2];
    const float* Wk = (const float*)d_in[3];
    const float* W1 = (const float*)d_in[4];
    const float* W2 = (const float*)d_in[5];
    float* out = (float*)d_out;

    k_mean<<<BB*CC, FF>>>(x);

    dim3 g2(FF/64, (BB*CC)/64);
    k_proj<<<g2, 256>>>(Wq, bq, Wk);

    const int smem3 = CC * 65 * sizeof(float);
    cudaFuncSetAttribute(k_attn, cudaFuncAttributeMaxDynamicSharedMemorySize, smem3);
    k_attn<<<BB*HH*(CC/32), 1024, smem3>>>();

    k_se2<<<BB, 256>>>(W1, W2);

    cudaFuncSetAttribute(k_wv, cudaFuncAttributeMaxDynamicSharedMemorySize, SMEM_WV);
    dim3 g5((TT*DH)/128, 1, BB*HH);
    k_wv<<<g5, 256, SMEM_WV>>>(x, out);
}